// round 3
// baseline (speedup 1.0000x reference)
#include <cuda_runtime.h>
#include <stdint.h>
#include <cub/block/block_radix_sort.cuh>

#define BN 64
#define GN 4999
#define PN 50
#define PW 157            // ceil(4999/32)
#define SEG 157           // positions per lane
#define GSTRIDE 5024      // 32*157, padded row stride
#define PPB 10            // pathways per es block
#define NPART 5           // PN / PPB

__device__ __align__(16) int      d_order[BN * GSTRIDE];
__device__ __align__(16) float    d_w[BN * GSTRIDE];
__device__ __align__(16) unsigned d_pbits[PN * PW];
__device__ int d_psize[PN];

// ---------------------------------------------------------------------------
// Kernel 1: per-sample descending stable sort. cub BlockRadixSort, radix-6
// (8 passes over 45 key bits), 1024 threads, TempStorage in dynamic smem.
// Key = (descending-monotone float bits << 13) | index.
// ---------------------------------------------------------------------------
#define SORT_THREADS 1024
#define SORT_ITEMS   5    // 5120 slots >= 4999

typedef cub::BlockRadixSort<unsigned long long, SORT_THREADS, SORT_ITEMS,
                            cub::NullType, 6> SorterT;

__global__ void __launch_bounds__(SORT_THREADS, 1)
sort_kernel(const float* __restrict__ expr) {
    extern __shared__ char dsm[];
    typename SorterT::TempStorage& ts =
        *reinterpret_cast<typename SorterT::TempStorage*>(dsm);

    const int b = blockIdx.x;
    const int t = threadIdx.x;
    const float* row = expr + (size_t)b * GN;

    unsigned long long k[SORT_ITEMS];
    #pragma unroll
    for (int j = 0; j < SORT_ITEMS; j++) {
        int i = j * SORT_THREADS + t;            // striped (coalesced) load
        if (i < GN) {
            unsigned u = __float_as_uint(row[i]);
            u = (u & 0x80000000u) ? ~u : (u | 0x80000000u);   // ascending map
            unsigned dsc = ~u;                                 // descending
            k[j] = ((unsigned long long)dsc << 13) | (unsigned)i;
        } else {
            k[j] = 0xFFFFFFFFFFFFFFFFull;
        }
    }

    SorterT(ts).Sort(k, 0, 45);

    #pragma unroll
    for (int j = 0; j < SORT_ITEMS; j++) {
        int pos = t * SORT_ITEMS + j;            // blocked after sort
        if (pos < GN) {
            int idx = (int)(k[j] & 0x1FFFull);
            unsigned dsc = (unsigned)(k[j] >> 13);
            unsigned u   = ~dsc;
            unsigned absbits = (u & 0x80000000u) ? (u & 0x7FFFFFFFu)
                                                 : ((~u) & 0x7FFFFFFFu);
            float af = __uint_as_float(absbits);
            d_order[b * GSTRIDE + pos] = idx;
            d_w[b * GSTRIDE + pos]     = sqrtf(sqrtf(af));   // |x|^0.25
        } else if (pos < GSTRIDE) {
            d_order[b * GSTRIDE + pos] = 0;                  // pad: hit, w=0
            d_w[b * GSTRIDE + pos]     = 0.0f;
        }
    }
}

// ---------------------------------------------------------------------------
// Kernel 2: pathway bitmask + size. One block per pathway, ballot-based.
// ---------------------------------------------------------------------------
__global__ void pbuild_kernel(const float* __restrict__ pw) {
    const int p    = blockIdx.x;
    const int tid  = threadIdx.x;     // 256
    const int wid  = tid >> 5;
    const int lane = tid & 31;
    __shared__ int wcnt[8];

    int local = 0;
    for (int wi = wid; wi < PW; wi += 8) {
        int g = wi * 32 + lane;
        bool hit = (g < GN) && (pw[(size_t)p * GN + g] > 0.0f);
        unsigned bits = __ballot_sync(0xffffffffu, hit);
        if (lane == 0) d_pbits[p * PW + wi] = bits;
        local += hit ? 1 : 0;
    }
    #pragma unroll
    for (int off = 16; off; off >>= 1) local += __shfl_down_sync(0xffffffffu, local, off);
    if (lane == 0) wcnt[wid] = local;
    __syncthreads();
    if (tid == 0) {
        int s = 0;
        #pragma unroll
        for (int i = 0; i < 8; i++) s += wcnt[i];
        d_psize[p] = s;
    }
}

// ---------------------------------------------------------------------------
// Kernel 3: enrichment. Grid (BN, NPART), 10 warps/block, 1 warp = 1 pathway.
// Lane owns a contiguous 157-elem segment (stride-157 smem: conflict-free).
// Pass A: per-lane hit-weight sum + hit bits cached in 5 registers.
// Pass B: replay bits from registers, serial running sum, first-argmax |r|.
// Padded tail positions (>= GN) are forced-hit with w=0 -> no-ops.
// ---------------------------------------------------------------------------
__global__ void __launch_bounds__(320, 4)
es_kernel(float* __restrict__ out) {
    extern __shared__ char smem[];
    int*      s_order = (int*)smem;                   // GSTRIDE
    float*    s_w     = (float*)(s_order + GSTRIDE);  // GSTRIDE
    unsigned* s_pb    = (unsigned*)(s_w + GSTRIDE);   // PPB*PW

    const int b    = blockIdx.x;
    const int part = blockIdx.y;
    const int p0   = part * PPB;
    const int tid  = threadIdx.x;

    {
        const int4* go = (const int4*)(d_order + b * GSTRIDE);
        const int4* gw = (const int4*)(d_w     + b * GSTRIDE);
        int4* so = (int4*)s_order;
        int4* sw = (int4*)s_w;
        for (int i = tid; i < GSTRIDE / 4; i += 320) { so[i] = go[i]; sw[i] = gw[i]; }
        for (int i = tid; i < PPB * PW; i += 320) s_pb[i] = d_pbits[p0 * PW + i];
    }
    __syncthreads();

    const int wid  = tid >> 5;
    const int lane = tid & 31;
    const int p    = p0 + wid;
    const unsigned* pb = s_pb + wid * PW;
    const int start = lane * SEG;

    // ---- pass A: hit bits -> registers; hit-weight sum ----
    unsigned hb[5];
    float hw = 0.0f;
    #pragma unroll
    for (int wi = 0; wi < 5; wi++) {
        const int cnt = (wi == 4) ? 29 : 32;   // 4*32 + 29 = 157
        unsigned bits = 0;
        #pragma unroll
        for (int q = 0; q < cnt; q++) {
            int i = start + wi * 32 + q;
            int g = s_order[i];
            unsigned hit = (pb[g >> 5] >> (g & 31)) & 1u;
            bits |= hit << q;
            if (hit) hw += s_w[i];
        }
        // pad positions (i >= GN, only lane 31 word 4, q >= 4) are forced hits
        if (wi == 4 && lane == 31) bits |= 0x1FFFFFF0u;
        hb[wi] = bits;
    }
    int hits = __popc(hb[0]) + __popc(hb[1]) + __popc(hb[2]) +
               __popc(hb[3]) + __popc(hb[4]);
    int mc = SEG - hits;   // pads are hits -> not counted as misses

    // total hit weight S across warp
    float S = hw;
    #pragma unroll
    for (int off = 16; off; off >>= 1) S += __shfl_xor_sync(0xffffffffu, S, off);

    const int   size      = d_psize[p];
    const float inv_denom = 1.0f / fmaxf((float)(GN - size), 1.0f);
    const float invS      = (S > 0.0f) ? (1.0f / S) : 1.0f;

    // exclusive prefix of per-lane net delta -> lane's starting r
    float lane_delta = hw * invS - (float)mc * inv_denom;
    float v = lane_delta;
    #pragma unroll
    for (int off = 1; off < 32; off <<= 1) {
        float t = __shfl_up_sync(0xffffffffu, v, off);
        if (lane >= off) v += t;
    }
    float r = v - lane_delta;   // exclusive prefix

    // ---- pass B: replay bits, track first argmax |r| ----
    float best_abs = -1.0f, best_val = 0.0f;
    int   best_idx = 0x7fffffff;
    #pragma unroll
    for (int wi = 0; wi < 5; wi++) {
        unsigned bits = hb[wi];
        const int cnt = (wi == 4) ? 29 : 32;
        #pragma unroll
        for (int q = 0; q < cnt; q++) {
            int i = start + wi * 32 + q;
            float wv = s_w[i];
            r = (bits & (1u << q)) ? fmaf(wv, invS, r) : (r - inv_denom);
            float ar = fabsf(r);
            bool better = ar > best_abs;
            best_abs = better ? ar : best_abs;
            best_val = better ? r  : best_val;
            best_idx = better ? i  : best_idx;
        }
    }

    // ---- cross-lane argmax reduce (tie -> smallest index) ----
    #pragma unroll
    for (int off = 16; off; off >>= 1) {
        float oa = __shfl_down_sync(0xffffffffu, best_abs, off);
        float ov = __shfl_down_sync(0xffffffffu, best_val, off);
        int   oi = __shfl_down_sync(0xffffffffu, best_idx, off);
        if (oa > best_abs || (oa == best_abs && oi < best_idx)) {
            best_abs = oa; best_val = ov; best_idx = oi;
        }
    }
    if (lane == 0) out[b * PN + p] = (size > 0) ? best_val : 0.0f;
}

// ---------------------------------------------------------------------------
extern "C" void kernel_launch(void* const* d_in, const int* in_sizes, int n_in,
                              void* d_out, int out_size) {
    const float* expr = (const float*)d_in[0];   // [B, G]
    const float* pw   = (const float*)d_in[1];   // [P, G]
    float* out        = (float*)d_out;           // [B, P]

    const int sort_smem = (int)sizeof(typename SorterT::TempStorage);
    const int es_smem   = GSTRIDE * 8 + PPB * PW * 4;   // 46472 B

    cudaFuncSetAttribute(sort_kernel, cudaFuncAttributeMaxDynamicSharedMemorySize, sort_smem);
    cudaFuncSetAttribute(es_kernel,   cudaFuncAttributeMaxDynamicSharedMemorySize, es_smem);

    pbuild_kernel<<<PN, 256>>>(pw);
    sort_kernel<<<BN, SORT_THREADS, sort_smem>>>(expr);
    es_kernel<<<dim3(BN, NPART), 320, es_smem>>>(out);
}

// round 4
// speedup vs baseline: 1.2580x; 1.2580x over previous
#include <cuda_runtime.h>
#include <stdint.h>
#include <cub/block/block_radix_sort.cuh>

#define BN 64
#define GN 4999
#define PN 50
#define PW 157            // ceil(4999/32)
#define SEG 157           // positions per lane
#define GSTRIDE 5024      // 32*157, padded row stride
#define PPB 25            // pathways per es block
#define NPART 2           // PN / PPB

__device__ __align__(16) int      d_order[BN * GSTRIDE];
__device__ __align__(16) float    d_w[BN * GSTRIDE];
__device__ __align__(16) unsigned d_pbits[PN * PW];

// ---------------------------------------------------------------------------
// Kernel 1: per-sample descending stable sort. cub BlockRadixSort, radix-6
// (8 passes over 45 key bits), 1024 threads, TempStorage in dynamic smem.
// Key = (descending-monotone float bits << 13) | index.
// ---------------------------------------------------------------------------
#define SORT_THREADS 1024
#define SORT_ITEMS   5    // 5120 slots >= 4999

typedef cub::BlockRadixSort<unsigned long long, SORT_THREADS, SORT_ITEMS,
                            cub::NullType, 6> SorterT;

__global__ void __launch_bounds__(SORT_THREADS, 1)
sort_kernel(const float* __restrict__ expr) {
    extern __shared__ char dsm[];
    typename SorterT::TempStorage& ts =
        *reinterpret_cast<typename SorterT::TempStorage*>(dsm);

    const int b = blockIdx.x;
    const int t = threadIdx.x;
    const float* row = expr + (size_t)b * GN;

    unsigned long long k[SORT_ITEMS];
    #pragma unroll
    for (int j = 0; j < SORT_ITEMS; j++) {
        int i = j * SORT_THREADS + t;            // striped (coalesced) load
        if (i < GN) {
            unsigned u = __float_as_uint(row[i]);
            u = (u & 0x80000000u) ? ~u : (u | 0x80000000u);   // ascending map
            unsigned dsc = ~u;                                 // descending
            k[j] = ((unsigned long long)dsc << 13) | (unsigned)i;
        } else {
            k[j] = 0xFFFFFFFFFFFFFFFFull;
        }
    }

    SorterT(ts).Sort(k, 0, 45);

    #pragma unroll
    for (int j = 0; j < SORT_ITEMS; j++) {
        int pos = t * SORT_ITEMS + j;            // blocked after sort
        if (pos < GN) {
            int idx = (int)(k[j] & 0x1FFFull);
            unsigned dsc = (unsigned)(k[j] >> 13);
            unsigned u   = ~dsc;
            unsigned absbits = (u & 0x80000000u) ? (u & 0x7FFFFFFFu)
                                                 : ((~u) & 0x7FFFFFFFu);
            float af = __uint_as_float(absbits);
            d_order[b * GSTRIDE + pos] = idx;
            d_w[b * GSTRIDE + pos]     = sqrtf(sqrtf(af));   // |x|^0.25
        } else if (pos < GSTRIDE) {
            d_order[b * GSTRIDE + pos] = 0;                  // pad (forced hit, w=0)
            d_w[b * GSTRIDE + pos]     = 0.0f;
        }
    }
}

// ---------------------------------------------------------------------------
// Kernel 2: pathway bitmask. One warp per (pathway, 32-gene word):
// one coalesced load + one ballot + one store. Fully latency-parallel.
// ---------------------------------------------------------------------------
__global__ void pbuild_kernel(const float* __restrict__ pw) {
    const int p    = blockIdx.x;
    const int part = blockIdx.y;                  // 0..4
    const int wid  = threadIdx.x >> 5;            // 0..31
    const int lane = threadIdx.x & 31;
    const int word = part * 32 + wid;
    if (word >= PW) return;
    const int g = word * 32 + lane;
    bool hit = (g < GN) && (pw[(size_t)p * GN + g] > 0.0f);
    unsigned bits = __ballot_sync(0xffffffffu, hit);
    if (lane == 0) d_pbits[p * PW + word] = bits;
}

// ---------------------------------------------------------------------------
// Kernel 3: enrichment. Grid (BN, NPART), 1024 threads, warps 0..24 each own
// one pathway. Lane owns a contiguous 157-elem segment (stride-157 smem:
// 157 coprime to 32 => conflict-free).
// Pass A: probe hits, accumulate hit-weight, stash hit bits in smem (5 words).
// Pass B: replay bits from smem, serial running sum, first-argmax |r|.
// Pad positions (>= GN) are forced hits with w=0 -> no-ops.
// ---------------------------------------------------------------------------
__global__ void __launch_bounds__(1024, 1)
es_kernel(float* __restrict__ out) {
    extern __shared__ char smem[];
    int*      s_order = (int*)smem;                   // GSTRIDE
    float*    s_w     = (float*)(s_order + GSTRIDE);  // GSTRIDE
    unsigned* s_pb    = (unsigned*)(s_w + GSTRIDE);   // PPB*PW
    unsigned* s_hb    = s_pb + PPB * PW;              // PPB*32*5

    const int b    = blockIdx.x;
    const int part = blockIdx.y;
    const int p0   = part * PPB;
    const int tid  = threadIdx.x;

    {
        const int4* go = (const int4*)(d_order + b * GSTRIDE);
        const int4* gw = (const int4*)(d_w     + b * GSTRIDE);
        int4* so = (int4*)s_order;
        int4* sw = (int4*)s_w;
        for (int i = tid; i < GSTRIDE / 4; i += 1024) { so[i] = go[i]; sw[i] = gw[i]; }
        for (int i = tid; i < PPB * PW; i += 1024) s_pb[i] = d_pbits[p0 * PW + i];
    }
    __syncthreads();

    const int wid  = tid >> 5;
    const int lane = tid & 31;
    if (wid >= PPB) return;

    const unsigned* pb = s_pb + wid * PW;
    unsigned* hbl = s_hb + (wid * 32 + lane) * 5;   // stride-5: conflict-free
    const int start = lane * SEG;

    // ---- pass A: probe hits -> smem bit words; hit-weight sum; popcount ----
    float hw = 0.0f;
    int hits = 0;
    #pragma unroll
    for (int wi = 0; wi < 5; wi++) {
        const int cnt = (wi == 4) ? 29 : 32;   // 4*32 + 29 = 157
        unsigned bits = 0;
        #pragma unroll
        for (int q = 0; q < cnt; q++) {
            int i = start + wi * 32 + q;
            int g = s_order[i];
            unsigned hit = (pb[g >> 5] >> (g & 31)) & 1u;
            bits |= hit << q;
            if (hit) hw += s_w[i];
        }
        // pad positions (i >= GN): lane 31, word 4, q >= 4 -> force hit (w=0)
        if (wi == 4 && lane == 31) bits |= 0x1FFFFFF0u;
        hbl[wi] = bits;
        hits += __popc(bits);
    }
    int mc = SEG - hits;

    // warp totals: S (hit weight) and pathway size (= total hits - 25 pads)
    float S = hw;
    int   th = hits;
    #pragma unroll
    for (int off = 16; off; off >>= 1) {
        S  += __shfl_xor_sync(0xffffffffu, S, off);
        th += __shfl_xor_sync(0xffffffffu, th, off);
    }
    const int size = th - 25;

    const float inv_denom = 1.0f / fmaxf((float)(GN - size), 1.0f);
    const float invS      = (S > 0.0f) ? (1.0f / S) : 1.0f;

    // exclusive prefix of per-lane net delta -> lane's starting r
    float lane_delta = hw * invS - (float)mc * inv_denom;
    float v = lane_delta;
    #pragma unroll
    for (int off = 1; off < 32; off <<= 1) {
        float t = __shfl_up_sync(0xffffffffu, v, off);
        if (lane >= off) v += t;
    }
    float r = v - lane_delta;   // exclusive prefix

    // ---- pass B: replay bits, track first argmax |r| ----
    float best_abs = -1.0f, best_val = 0.0f;
    int   best_idx = 0x7fffffff;
    #pragma unroll
    for (int wi = 0; wi < 5; wi++) {
        unsigned bits = hbl[wi];
        const int cnt = (wi == 4) ? 29 : 32;
        #pragma unroll
        for (int q = 0; q < cnt; q++) {
            int i = start + wi * 32 + q;
            float wv = s_w[i];
            r = (bits & (1u << q)) ? fmaf(wv, invS, r) : (r - inv_denom);
            float ar = fabsf(r);
            bool better = ar > best_abs;
            best_abs = better ? ar : best_abs;
            best_val = better ? r  : best_val;
            best_idx = better ? i  : best_idx;
        }
    }

    // ---- cross-lane argmax reduce (tie -> smallest index) ----
    #pragma unroll
    for (int off = 16; off; off >>= 1) {
        float oa = __shfl_down_sync(0xffffffffu, best_abs, off);
        float ov = __shfl_down_sync(0xffffffffu, best_val, off);
        int   oi = __shfl_down_sync(0xffffffffu, best_idx, off);
        if (oa > best_abs || (oa == best_abs && oi < best_idx)) {
            best_abs = oa; best_val = ov; best_idx = oi;
        }
    }
    if (lane == 0) out[b * PN + p0 + wid] = (size > 0) ? best_val : 0.0f;
}

// ---------------------------------------------------------------------------
extern "C" void kernel_launch(void* const* d_in, const int* in_sizes, int n_in,
                              void* d_out, int out_size) {
    const float* expr = (const float*)d_in[0];   // [B, G]
    const float* pw   = (const float*)d_in[1];   // [P, G]
    float* out        = (float*)d_out;           // [B, P]

    const int sort_smem = (int)sizeof(typename SorterT::TempStorage);
    const int es_smem   = GSTRIDE * 8 + PPB * PW * 4 + PPB * 32 * 5 * 4;  // ~72 KB

    cudaFuncSetAttribute(sort_kernel, cudaFuncAttributeMaxDynamicSharedMemorySize, sort_smem);
    cudaFuncSetAttribute(es_kernel,   cudaFuncAttributeMaxDynamicSharedMemorySize, es_smem);

    pbuild_kernel<<<dim3(PN, 5), 1024>>>(pw);
    sort_kernel<<<BN, SORT_THREADS, sort_smem>>>(expr);
    es_kernel<<<dim3(BN, NPART), 1024, es_smem>>>(out);
}